// round 7
// baseline (speedup 1.0000x reference)
#include <cuda_runtime.h>

#define BB 4
#define LL 1024
#define VV 1280
#define NE 768
#define NB 8
#define NH 32
#define NO 256          // NB*NH
#define NC 32           // chunks over L
#define CH 32           // chunk size (NC*CH == LL)

typedef unsigned long long ull;

// packed fp32x2 FMA (SASS FFMA2) — PTX-only; IEEE-identical to 2x fmaf
__device__ __forceinline__ ull ffma2(ull a, ull b, ull c) {
    ull d;
    asm("fma.rn.f32x2 %0, %1, %2, %3;" : "=l"(d) : "l"(a), "l"(b), "l"(c));
    return d;
}

// Scratch (device globals: no allocation allowed)
__device__ float g_x[BB * LL * NO];           // 4 MB  : x = h @ W1
__device__ int   g_chunk_first[BB * NC * VV]; // 640 KB
__device__ int   g_next[BB * NC * VV];        // 640 KB

// ---------------------------------------------------------------------------
// GEMM1: x[4096,256] = h[4096,768] @ W1[768,256]
// Block 128m x 64n, 256 threads (8 warps), BK=16. Thread tile 8m x 4n.
// (unchanged from R6 — working, not the measured bottleneck)
// ---------------------------------------------------------------------------
__global__ __launch_bounds__(256) void gemm1_kernel(
    const float* __restrict__ h, const float* __restrict__ W1)
{
    __shared__ float As_dup[16][256];   // [k][2*m] : 16 KB
    __shared__ float Bs[16][64];        // [k][n]   :  4 KB

    const int tid = threadIdx.x;
    const int tx = tid & 15;            // n group: 4 n each
    const int ty = tid >> 4;            // m group: 8 m each (0..15)
    const int m0 = blockIdx.y * 128;
    const int n0 = blockIdx.x * 64;

    const int ar = tid >> 1;            // 0..127 (m for A staging)
    const int ac = (tid & 1) * 8;       // 0 or 8 (k offset)
    const int br = tid >> 4;            // 0..15  (k for B staging)
    const int bc = (tid & 15) * 4;      // n offset

    ull acc[8][2];                      // [m][n-pair]
#pragma unroll
    for (int i = 0; i < 8; ++i) { acc[i][0] = 0ULL; acc[i][1] = 0ULL; }

    for (int k0 = 0; k0 < NE; k0 += 16) {
#pragma unroll
        for (int half = 0; half < 2; ++half) {
            float4 av = *(const float4*)&h[(m0 + ar) * NE + k0 + ac + half * 4];
            ((float2*)As_dup[ac + half * 4 + 0])[ar] = make_float2(av.x, av.x);
            ((float2*)As_dup[ac + half * 4 + 1])[ar] = make_float2(av.y, av.y);
            ((float2*)As_dup[ac + half * 4 + 2])[ar] = make_float2(av.z, av.z);
            ((float2*)As_dup[ac + half * 4 + 3])[ar] = make_float2(av.w, av.w);
        }
        *(float4*)&Bs[br][bc] = *(const float4*)&W1[(k0 + br) * NO + n0 + bc];
        __syncthreads();

#pragma unroll
        for (int kk = 0; kk < 16; ++kk) {
            const ull* arow = (const ull*)As_dup[kk];   // 128 dup-pairs
            const ull* brow = (const ull*)Bs[kk];       // 32 natural pairs
            ulonglong2 t0 = *(const ulonglong2*)&arow[ty * 8 + 0];
            ulonglong2 t1 = *(const ulonglong2*)&arow[ty * 8 + 2];
            ulonglong2 t2 = *(const ulonglong2*)&arow[ty * 8 + 4];
            ulonglong2 t3 = *(const ulonglong2*)&arow[ty * 8 + 6];
            ulonglong2 u  = *(const ulonglong2*)&brow[tx * 2];
            ull a_[8] = {t0.x, t0.y, t1.x, t1.y, t2.x, t2.y, t3.x, t3.y};
#pragma unroll
            for (int i = 0; i < 8; ++i) {
                acc[i][0] = ffma2(a_[i], u.x, acc[i][0]);
                acc[i][1] = ffma2(a_[i], u.y, acc[i][1]);
            }
        }
        __syncthreads();
    }

#pragma unroll
    for (int i = 0; i < 8; ++i) {
        *(ulonglong2*)&g_x[(m0 + ty * 8 + i) * NO + n0 + tx * 4] =
            make_ulonglong2(acc[i][0], acc[i][1]);
    }
}

// ---------------------------------------------------------------------------
// GEMM2: logits[m][n][v] = sum_h x[m][n*32+h] * W2[h][v]
// Block: 16 m-rows x 128 v x all 8 bins. 256 threads = 8 warps.
// Warp wid owns m-rows {2wid, 2wid+1}; lane owns 4 v (2 f32x2 pairs).
// w loads amortized over 2 m-rows -> smem wf/FFMA2 = 0.375 (was 0.5).
// acc = 2m x 8n x 2vp = 32 ull (64 regs).
// ---------------------------------------------------------------------------
__global__ __launch_bounds__(256, 2) void gemm2_kernel(
    const float* __restrict__ W2, float* __restrict__ logits)
{
    __shared__ float  W2s[32][128];     // 16 KB
    __shared__ float2 xs[16 * 256];     // 32 KB, dup'd {x,x}

    const int tid = threadIdx.x;
    const int v0 = blockIdx.x * 128;
    const int m0 = blockIdx.y * 16;
    const int wid = tid >> 5;           // 0..7
    const int lane = tid & 31;
    const int vloc = lane * 4;

    // stage W2 tile: 32 x 128
#pragma unroll
    for (int it = 0; it < 4; ++it) {
        int f4 = tid + it * 256;        // 0..1023 float4s
        int r = f4 >> 5;                // 0..31
        int c = (f4 & 31) * 4;
        *(float4*)&W2s[r][c] = *(const float4*)&W2[r * VV + v0 + c];
    }
    // stage x duplicated: 16 rows x 256
#pragma unroll
    for (int it = 0; it < 16; ++it) {
        int idx = tid + it * 256;       // 0..4095
        int r = idx >> 8;
        int c = idx & 255;
        float v = g_x[(m0 + r) * NO + c];
        xs[r * 256 + c] = make_float2(v, v);
    }
    __syncthreads();

    ull acc[2][8][2];
#pragma unroll
    for (int mi = 0; mi < 2; ++mi)
#pragma unroll
        for (int n = 0; n < 8; ++n) { acc[mi][n][0] = 0ULL; acc[mi][n][1] = 0ULL; }

    const ull* xrow0 = (const ull*)&xs[(wid * 2 + 0) * 256];
    const ull* xrow1 = (const ull*)&xs[(wid * 2 + 1) * 256];

#pragma unroll
    for (int h4 = 0; h4 < 8; ++h4) {
        const int hh = h4 * 4;
        ull w_[4][2];
#pragma unroll
        for (int j = 0; j < 4; ++j) {
            ulonglong2 wt = *(const ulonglong2*)&W2s[hh + j][vloc];
            w_[j][0] = wt.x; w_[j][1] = wt.y;
        }
#pragma unroll
        for (int n = 0; n < 8; ++n) {
            ulonglong2 x0 = *(const ulonglong2*)&xrow0[n * 32 + hh];
            ulonglong2 x1 = *(const ulonglong2*)&xrow0[n * 32 + hh + 2];
            acc[0][n][0] = ffma2(x0.x, w_[0][0], acc[0][n][0]);
            acc[0][n][1] = ffma2(x0.x, w_[0][1], acc[0][n][1]);
            acc[0][n][0] = ffma2(x0.y, w_[1][0], acc[0][n][0]);
            acc[0][n][1] = ffma2(x0.y, w_[1][1], acc[0][n][1]);
            acc[0][n][0] = ffma2(x1.x, w_[2][0], acc[0][n][0]);
            acc[0][n][1] = ffma2(x1.x, w_[2][1], acc[0][n][1]);
            acc[0][n][0] = ffma2(x1.y, w_[3][0], acc[0][n][0]);
            acc[0][n][1] = ffma2(x1.y, w_[3][1], acc[0][n][1]);

            ulonglong2 y0 = *(const ulonglong2*)&xrow1[n * 32 + hh];
            ulonglong2 y1 = *(const ulonglong2*)&xrow1[n * 32 + hh + 2];
            acc[1][n][0] = ffma2(y0.x, w_[0][0], acc[1][n][0]);
            acc[1][n][1] = ffma2(y0.x, w_[0][1], acc[1][n][1]);
            acc[1][n][0] = ffma2(y0.y, w_[1][0], acc[1][n][0]);
            acc[1][n][1] = ffma2(y0.y, w_[1][1], acc[1][n][1]);
            acc[1][n][0] = ffma2(y1.x, w_[2][0], acc[1][n][0]);
            acc[1][n][1] = ffma2(y1.x, w_[2][1], acc[1][n][1]);
            acc[1][n][0] = ffma2(y1.y, w_[3][0], acc[1][n][0]);
            acc[1][n][1] = ffma2(y1.y, w_[3][1], acc[1][n][1]);
        }
    }

#pragma unroll
    for (int mi = 0; mi < 2; ++mi) {
        const int m = m0 + wid * 2 + mi;
#pragma unroll
        for (int n = 0; n < 8; ++n) {
            *(ulonglong2*)&logits[(m * NB + n) * VV + v0 + vloc] =
                make_ulonglong2(acc[mi][n][0], acc[mi][n][1]);
        }
    }
}

// ---------------------------------------------------------------------------
// Kernel A: per-chunk first occurrence. Block per (b, c); smem atomicMin.
// ---------------------------------------------------------------------------
__global__ __launch_bounds__(256) void first_occ_kernel(const int* __restrict__ targets)
{
    __shared__ int arr[VV];
    const int b = blockIdx.x >> 5;
    const int c = blockIdx.x & 31;
    const int tid = threadIdx.x;

#pragma unroll
    for (int it = 0; it < 5; ++it) arr[tid + it * 256] = LL;
    __syncthreads();
    if (tid < CH) {
        int j = c * CH + tid;
        atomicMin(&arr[targets[b * LL + j]], j);
    }
    __syncthreads();
#pragma unroll
    for (int it = 0; it < 5; ++it) {
        int idx = tid + it * 256;
        g_chunk_first[(b * NC + c) * VV + idx] = arr[idx];
    }
}

// ---------------------------------------------------------------------------
// Kernel B: exclusive suffix-min over chunks. One thread per (b, v).
// ---------------------------------------------------------------------------
__global__ __launch_bounds__(256) void suffix_kernel()
{
    const int gt = blockIdx.x * 256 + threadIdx.x;   // 0..5119
    const int b = gt / VV;
    const int v = gt - b * VV;

    int cf[NC];
#pragma unroll
    for (int c = 0; c < NC; ++c) cf[c] = g_chunk_first[(b * NC + c) * VV + v];

    int run = LL;
#pragma unroll
    for (int c = NC - 1; c >= 0; --c) {
        g_next[(b * NC + c) * VV + v] = run;
        run = min(run, cf[c]);
    }
}

// ---------------------------------------------------------------------------
// Kernel C: tte + censor mask. Block per (b, c, vhalf), 160 threads, 4 v each.
// ---------------------------------------------------------------------------
__global__ __launch_bounds__(160) void tte_mask_kernel(
    const int* __restrict__ targets,
    const float* __restrict__ age,
    const float* __restrict__ targets_age,
    float* __restrict__ out_tte,
    float* __restrict__ out_mask)
{
    __shared__ float ta_s[LL];
    __shared__ int ts[CH];
    __shared__ float ag[CH];

    const int b = blockIdx.x >> 6;
    const int rem = blockIdx.x & 63;
    const int c = rem >> 1;
    const int half = rem & 1;
    const int tid = threadIdx.x;        // 0..159

    for (int idx = tid; idx < LL; idx += 160)
        ta_s[idx] = targets_age[b * LL + idx];
    if (tid < CH) {
        int i = c * CH + tid;
        ts[tid] = targets[b * LL + i];
        ag[tid] = age[b * LL + i];
    }
    __syncthreads();

    const int vb = half * 640 + tid * 4;
    int4 c4 = *(const int4*)&g_next[(b * NC + c) * VV + vb];
    int cur0 = c4.x, cur1 = c4.y, cur2 = c4.z, cur3 = c4.w;

    for (int jj = CH - 1; jj >= 0; --jj) {
        const int i = c * CH + jj;
        const int t = ts[jj];
        const float ai = ag[jj];

        if (t == vb + 0) cur0 = i;
        if (t == vb + 1) cur1 = i;
        if (t == vb + 2) cur2 = i;
        if (t == vb + 3) cur3 = i;

        float tte[4];
        bool nev[4];
        int curs[4] = {cur0, cur1, cur2, cur3};
#pragma unroll
        for (int q = 0; q < 4; ++q) {
            int vv = vb + q;
            int idxr = curs[q];
            if (vv == 0 && i > 0) idxr = 0;  // reference's where(upper, targets, 0) quirk
            bool ne = (idxr == LL);
            int idx = ne ? (LL - 1) : idxr;
            tte[q] = ta_s[idx] - ai;
            nev[q] = ne;
        }

        const int row = b * LL + i;
        *(float4*)&out_tte[row * VV + vb] = make_float4(tte[0], tte[1], tte[2], tte[3]);

        int bin[4];
        bool valid[4];
#pragma unroll
        for (int q = 0; q < 4; ++q) {
            float tq = tte[q];
            valid[q] = (tq >= 0.0f) && (tq < 10.0f);
            bin[q] = (tq >= 1.25f) + (tq >= 2.5f) + (tq >= 3.75f) + (tq >= 5.0f)
                   + (tq >= 6.25f) + (tq >= 7.5f) + (tq >= 8.75f);
        }

        const int mbase = row * NB * VV + vb;
#pragma unroll
        for (int n = 0; n < 8; ++n) {
            float4 mv;
            mv.x = (nev[0] || (valid[0] && bin[0] == n)) ? 1.0f : 0.0f;
            mv.y = (nev[1] || (valid[1] && bin[1] == n)) ? 1.0f : 0.0f;
            mv.z = (nev[2] || (valid[2] && bin[2] == n)) ? 1.0f : 0.0f;
            mv.w = (nev[3] || (valid[3] && bin[3] == n)) ? 1.0f : 0.0f;
            *(float4*)&out_mask[mbase + n * VV] = mv;
        }
    }
}

// ---------------------------------------------------------------------------
extern "C" void kernel_launch(void* const* d_in, const int* in_sizes, int n_in,
                              void* d_out, int out_size)
{
    const float* h   = (const float*)d_in[0];  // (B,L,768) f32
    const float* age = (const float*)d_in[1];  // (B,L) f32
    const float* ta  = (const float*)d_in[2];  // (B,L) f32 targets_age
    // d_in[3] = delta_t (unused by outputs)
    const int*   tg  = (const int*)d_in[4];    // (B,L) i32 targets
    const float* W1  = (const float*)d_in[5];  // (768,256) f32
    const float* W2  = (const float*)d_in[6];  // (32,1280) f32

    float* out = (float*)d_out;
    float* out_logits = out;                                  // B*L*8*V
    float* out_tte    = out + (size_t)BB * LL * NB * VV;      // B*L*V
    float* out_mask   = out_tte + (size_t)BB * LL * VV;       // B*L*8*V

    // order chosen so the ncu-captured slot (4th of a replay) lands on gemm2
    first_occ_kernel<<<BB * NC, 256>>>(tg);
    gemm1_kernel<<<dim3(NO / 64, (BB * LL) / 128), 256>>>(h, W1);
    suffix_kernel<<<(BB * VV) / 256, 256>>>();
    gemm2_kernel<<<dim3(VV / 128, (BB * LL) / 16), 256>>>(W2, out_logits);
    tte_mask_kernel<<<BB * NC * 2, 160>>>(tg, age, ta, out_tte, out_mask);
}

// round 8
// speedup vs baseline: 1.0106x; 1.0106x over previous
#include <cuda_runtime.h>

#define BB 4
#define LL 1024
#define VV 1280
#define NE 768
#define NB 8
#define NH 32
#define NO 256          // NB*NH
#define NC 32           // chunks over L
#define CH 32           // chunk size (NC*CH == LL)

typedef unsigned long long ull;

// packed fp32x2 FMA (SASS FFMA2) — PTX-only; IEEE-identical to 2x fmaf
__device__ __forceinline__ ull ffma2(ull a, ull b, ull c) {
    ull d;
    asm("fma.rn.f32x2 %0, %1, %2, %3;" : "=l"(d) : "l"(a), "l"(b), "l"(c));
    return d;
}
// splat one f32 into a 64-bit pair {x,x} (register MOV, alu pipe)
__device__ __forceinline__ ull dup2(float x) {
    ull d;
    asm("mov.b64 %0, {%1, %1};" : "=l"(d) : "f"(x));
    return d;
}
__device__ __forceinline__ unsigned smem_u32(const void* p) {
    return (unsigned)__cvta_generic_to_shared(p);
}
__device__ __forceinline__ void cpasync16(unsigned dst, const void* src) {
    asm volatile("cp.async.ca.shared.global [%0], [%1], 16;" :: "r"(dst), "l"(src));
}

// Scratch (device globals: no allocation allowed)
__device__ float g_x[BB * LL * NO];           // 4 MB  : x = h @ W1
__device__ int   g_chunk_first[BB * NC * VV]; // 640 KB
__device__ int   g_next[BB * NC * VV];        // 640 KB

// ---------------------------------------------------------------------------
// GEMM1: x[4096,256] = h[4096,768] @ W1[768,256]  (unchanged, ~23us by model)
// ---------------------------------------------------------------------------
__global__ __launch_bounds__(256) void gemm1_kernel(
    const float* __restrict__ h, const float* __restrict__ W1)
{
    __shared__ float As_dup[16][256];
    __shared__ float Bs[16][64];

    const int tid = threadIdx.x;
    const int tx = tid & 15;
    const int ty = tid >> 4;
    const int m0 = blockIdx.y * 128;
    const int n0 = blockIdx.x * 64;

    const int ar = tid >> 1;
    const int ac = (tid & 1) * 8;
    const int br = tid >> 4;
    const int bc = (tid & 15) * 4;

    ull acc[8][2];
#pragma unroll
    for (int i = 0; i < 8; ++i) { acc[i][0] = 0ULL; acc[i][1] = 0ULL; }

    for (int k0 = 0; k0 < NE; k0 += 16) {
#pragma unroll
        for (int half = 0; half < 2; ++half) {
            float4 av = *(const float4*)&h[(m0 + ar) * NE + k0 + ac + half * 4];
            ((float2*)As_dup[ac + half * 4 + 0])[ar] = make_float2(av.x, av.x);
            ((float2*)As_dup[ac + half * 4 + 1])[ar] = make_float2(av.y, av.y);
            ((float2*)As_dup[ac + half * 4 + 2])[ar] = make_float2(av.z, av.z);
            ((float2*)As_dup[ac + half * 4 + 3])[ar] = make_float2(av.w, av.w);
        }
        *(float4*)&Bs[br][bc] = *(const float4*)&W1[(k0 + br) * NO + n0 + bc];
        __syncthreads();

#pragma unroll
        for (int kk = 0; kk < 16; ++kk) {
            const ull* arow = (const ull*)As_dup[kk];
            const ull* brow = (const ull*)Bs[kk];
            ulonglong2 t0 = *(const ulonglong2*)&arow[ty * 8 + 0];
            ulonglong2 t1 = *(const ulonglong2*)&arow[ty * 8 + 2];
            ulonglong2 t2 = *(const ulonglong2*)&arow[ty * 8 + 4];
            ulonglong2 t3 = *(const ulonglong2*)&arow[ty * 8 + 6];
            ulonglong2 u  = *(const ulonglong2*)&brow[tx * 2];
            ull a_[8] = {t0.x, t0.y, t1.x, t1.y, t2.x, t2.y, t3.x, t3.y};
#pragma unroll
            for (int i = 0; i < 8; ++i) {
                acc[i][0] = ffma2(a_[i], u.x, acc[i][0]);
                acc[i][1] = ffma2(a_[i], u.y, acc[i][1]);
            }
        }
        __syncthreads();
    }

#pragma unroll
    for (int i = 0; i < 8; ++i) {
        *(ulonglong2*)&g_x[(m0 + ty * 8 + i) * NO + n0 + tx * 4] =
            make_ulonglong2(acc[i][0], acc[i][1]);
    }
}

// ---------------------------------------------------------------------------
// GEMM2: logits[m][n][v] = sum_h x[m][n*32+h] * W2[h][v]
// Persistent block: 64 m-rows (4 chunks of 16) x 128 v, all 8 bins.
// cp.async double-buffered NATURAL x staging; W2 staged once.
// Warp owns 2 m-rows; lane owns 4 v (2 f32x2 pairs). x splat via reg MOV.
// ---------------------------------------------------------------------------
#define MCHUNK 16
#define NCHUNK 4
__global__ __launch_bounds__(256, 2) void gemm2_kernel(
    const float* __restrict__ W2, float* __restrict__ logits)
{
    __shared__ float W2s[32][128];              // 16 KB
    __shared__ float xsn[2][MCHUNK * 256];      // 2 x 16 KB, natural layout

    const int tid = threadIdx.x;
    const int v0 = blockIdx.x * 128;
    const int mb = blockIdx.y * 64;
    const int wid = tid >> 5;
    const int lane = tid & 31;
    const int vloc = lane * 4;

    // prologue: async-stage W2 tile (32x128) + chunk 0 of x (16x256)
#pragma unroll
    for (int s = 0; s < 4; ++s) {
        int idx = tid + s * 256;                // 0..1023 16B-segs
        int r = idx >> 5;
        int c = (idx & 31) * 4;
        cpasync16(smem_u32(&W2s[r][c]), &W2[r * VV + v0 + c]);
    }
    {
        const float* src = &g_x[mb * NO];       // chunk rows contiguous
#pragma unroll
        for (int s = 0; s < 4; ++s)
            cpasync16(smem_u32(&xsn[0][tid * 4 + s * 1024]), src + tid * 4 + s * 1024);
    }
    asm volatile("cp.async.commit_group;");

#pragma unroll 1
    for (int c = 0; c < NCHUNK; ++c) {
        if (c < NCHUNK - 1) {
            const float* src = &g_x[(mb + (c + 1) * MCHUNK) * NO];
            float* dst = xsn[(c + 1) & 1];
#pragma unroll
            for (int s = 0; s < 4; ++s)
                cpasync16(smem_u32(&dst[tid * 4 + s * 1024]), src + tid * 4 + s * 1024);
            asm volatile("cp.async.commit_group;");
            asm volatile("cp.async.wait_group 1;");
        } else {
            asm volatile("cp.async.wait_group 0;");
        }
        __syncthreads();

        const float* x0 = &xsn[c & 1][(wid * 2 + 0) * 256];
        const float* x1 = &xsn[c & 1][(wid * 2 + 1) * 256];

        ull acc[2][8][2];
#pragma unroll
        for (int mi = 0; mi < 2; ++mi)
#pragma unroll
            for (int n = 0; n < 8; ++n) { acc[mi][n][0] = 0ULL; acc[mi][n][1] = 0ULL; }

#pragma unroll
        for (int h4 = 0; h4 < 8; ++h4) {
            const int hh = h4 * 4;
            ull w_[4][2];
#pragma unroll
            for (int j = 0; j < 4; ++j) {
                ulonglong2 wt = *(const ulonglong2*)&W2s[hh + j][vloc];
                w_[j][0] = wt.x; w_[j][1] = wt.y;
            }
#pragma unroll
            for (int n = 0; n < 8; ++n) {
                float4 a = *(const float4*)&x0[n * 32 + hh];   // broadcast LDS.128
                ull p0 = dup2(a.x), p1 = dup2(a.y), p2 = dup2(a.z), p3 = dup2(a.w);
                acc[0][n][0] = ffma2(p0, w_[0][0], acc[0][n][0]);
                acc[0][n][1] = ffma2(p0, w_[0][1], acc[0][n][1]);
                acc[0][n][0] = ffma2(p1, w_[1][0], acc[0][n][0]);
                acc[0][n][1] = ffma2(p1, w_[1][1], acc[0][n][1]);
                acc[0][n][0] = ffma2(p2, w_[2][0], acc[0][n][0]);
                acc[0][n][1] = ffma2(p2, w_[2][1], acc[0][n][1]);
                acc[0][n][0] = ffma2(p3, w_[3][0], acc[0][n][0]);
                acc[0][n][1] = ffma2(p3, w_[3][1], acc[0][n][1]);

                float4 b = *(const float4*)&x1[n * 32 + hh];
                ull q0 = dup2(b.x), q1 = dup2(b.y), q2 = dup2(b.z), q3 = dup2(b.w);
                acc[1][n][0] = ffma2(q0, w_[0][0], acc[1][n][0]);
                acc[1][n][1] = ffma2(q0, w_[0][1], acc[1][n][1]);
                acc[1][n][0] = ffma2(q1, w_[1][0], acc[1][n][0]);
                acc[1][n][1] = ffma2(q1, w_[1][1], acc[1][n][1]);
                acc[1][n][0] = ffma2(q2, w_[2][0], acc[1][n][0]);
                acc[1][n][1] = ffma2(q2, w_[2][1], acc[1][n][1]);
                acc[1][n][0] = ffma2(q3, w_[3][0], acc[1][n][0]);
                acc[1][n][1] = ffma2(q3, w_[3][1], acc[1][n][1]);
            }
        }

#pragma unroll
        for (int mi = 0; mi < 2; ++mi) {
            const int m = mb + c * MCHUNK + wid * 2 + mi;
#pragma unroll
            for (int n = 0; n < 8; ++n) {
                *(ulonglong2*)&logits[(m * NB + n) * VV + v0 + vloc] =
                    make_ulonglong2(acc[mi][n][0], acc[mi][n][1]);
            }
        }
        __syncthreads();   // buffer c&1 free for chunk c+2's cp.async
    }
}

// ---------------------------------------------------------------------------
// Kernel A: per-chunk first occurrence. Block per (b, c); smem atomicMin.
// ---------------------------------------------------------------------------
__global__ __launch_bounds__(256) void first_occ_kernel(const int* __restrict__ targets)
{
    __shared__ int arr[VV];
    const int b = blockIdx.x >> 5;
    const int c = blockIdx.x & 31;
    const int tid = threadIdx.x;

#pragma unroll
    for (int it = 0; it < 5; ++it) arr[tid + it * 256] = LL;
    __syncthreads();
    if (tid < CH) {
        int j = c * CH + tid;
        atomicMin(&arr[targets[b * LL + j]], j);
    }
    __syncthreads();
#pragma unroll
    for (int it = 0; it < 5; ++it) {
        int idx = tid + it * 256;
        g_chunk_first[(b * NC + c) * VV + idx] = arr[idx];
    }
}

// ---------------------------------------------------------------------------
// Kernel B: exclusive suffix-min over chunks. One thread per (b, v).
// ---------------------------------------------------------------------------
__global__ __launch_bounds__(256) void suffix_kernel()
{
    const int gt = blockIdx.x * 256 + threadIdx.x;   // 0..5119
    const int b = gt / VV;
    const int v = gt - b * VV;

    int cf[NC];
#pragma unroll
    for (int c = 0; c < NC; ++c) cf[c] = g_chunk_first[(b * NC + c) * VV + v];

    int run = LL;
#pragma unroll
    for (int c = NC - 1; c >= 0; --c) {
        g_next[(b * NC + c) * VV + v] = run;
        run = min(run, cf[c]);
    }
}

// ---------------------------------------------------------------------------
// Kernel C: tte + censor mask. Block per (b, c, vhalf), 160 threads, 4 v each.
// ---------------------------------------------------------------------------
__global__ __launch_bounds__(160) void tte_mask_kernel(
    const int* __restrict__ targets,
    const float* __restrict__ age,
    const float* __restrict__ targets_age,
    float* __restrict__ out_tte,
    float* __restrict__ out_mask)
{
    __shared__ float ta_s[LL];
    __shared__ int ts[CH];
    __shared__ float ag[CH];

    const int b = blockIdx.x >> 6;
    const int rem = blockIdx.x & 63;
    const int c = rem >> 1;
    const int half = rem & 1;
    const int tid = threadIdx.x;        // 0..159

    for (int idx = tid; idx < LL; idx += 160)
        ta_s[idx] = targets_age[b * LL + idx];
    if (tid < CH) {
        int i = c * CH + tid;
        ts[tid] = targets[b * LL + i];
        ag[tid] = age[b * LL + i];
    }
    __syncthreads();

    const int vb = half * 640 + tid * 4;
    int4 c4 = *(const int4*)&g_next[(b * NC + c) * VV + vb];
    int cur0 = c4.x, cur1 = c4.y, cur2 = c4.z, cur3 = c4.w;

    for (int jj = CH - 1; jj >= 0; --jj) {
        const int i = c * CH + jj;
        const int t = ts[jj];
        const float ai = ag[jj];

        if (t == vb + 0) cur0 = i;
        if (t == vb + 1) cur1 = i;
        if (t == vb + 2) cur2 = i;
        if (t == vb + 3) cur3 = i;

        float tte[4];
        bool nev[4];
        int curs[4] = {cur0, cur1, cur2, cur3};
#pragma unroll
        for (int q = 0; q < 4; ++q) {
            int vv = vb + q;
            int idxr = curs[q];
            if (vv == 0 && i > 0) idxr = 0;  // reference's where(upper, targets, 0) quirk
            bool ne = (idxr == LL);
            int idx = ne ? (LL - 1) : idxr;
            tte[q] = ta_s[idx] - ai;
            nev[q] = ne;
        }

        const int row = b * LL + i;
        *(float4*)&out_tte[row * VV + vb] = make_float4(tte[0], tte[1], tte[2], tte[3]);

        int bin[4];
        bool valid[4];
#pragma unroll
        for (int q = 0; q < 4; ++q) {
            float tq = tte[q];
            valid[q] = (tq >= 0.0f) && (tq < 10.0f);
            bin[q] = (tq >= 1.25f) + (tq >= 2.5f) + (tq >= 3.75f) + (tq >= 5.0f)
                   + (tq >= 6.25f) + (tq >= 7.5f) + (tq >= 8.75f);
        }

        const int mbase = row * NB * VV + vb;
#pragma unroll
        for (int n = 0; n < 8; ++n) {
            float4 mv;
            mv.x = (nev[0] || (valid[0] && bin[0] == n)) ? 1.0f : 0.0f;
            mv.y = (nev[1] || (valid[1] && bin[1] == n)) ? 1.0f : 0.0f;
            mv.z = (nev[2] || (valid[2] && bin[2] == n)) ? 1.0f : 0.0f;
            mv.w = (nev[3] || (valid[3] && bin[3] == n)) ? 1.0f : 0.0f;
            *(float4*)&out_mask[mbase + n * VV] = mv;
        }
    }
}

// ---------------------------------------------------------------------------
extern "C" void kernel_launch(void* const* d_in, const int* in_sizes, int n_in,
                              void* d_out, int out_size)
{
    const float* h   = (const float*)d_in[0];  // (B,L,768) f32
    const float* age = (const float*)d_in[1];  // (B,L) f32
    const float* ta  = (const float*)d_in[2];  // (B,L) f32 targets_age
    // d_in[3] = delta_t (unused by outputs)
    const int*   tg  = (const int*)d_in[4];    // (B,L) i32 targets
    const float* W1  = (const float*)d_in[5];  // (768,256) f32
    const float* W2  = (const float*)d_in[6];  // (32,1280) f32

    float* out = (float*)d_out;
    float* out_logits = out;                                  // B*L*8*V
    float* out_tte    = out + (size_t)BB * LL * NB * VV;      // B*L*V
    float* out_mask   = out_tte + (size_t)BB * LL * VV;       // B*L*8*V

    // order chosen so the ncu-captured slot lands on gemm2
    first_occ_kernel<<<BB * NC, 256>>>(tg);
    gemm1_kernel<<<dim3(NO / 64, (BB * LL) / 128), 256>>>(h, W1);
    suffix_kernel<<<(BB * VV) / 256, 256>>>();
    gemm2_kernel<<<dim3(VV / 128, (BB * LL) / 64), 256>>>(W2, out_logits);
    tte_mask_kernel<<<BB * NC * 2, 160>>>(tg, age, ta, out_tte, out_mask);
}

// round 9
// speedup vs baseline: 1.1447x; 1.1327x over previous
#include <cuda_runtime.h>
#include <cuda_bf16.h>

#define BB 4
#define LL 1024
#define VV 1280
#define NE 768
#define NB 8
#define NH 32
#define NO 256          // NB*NH
#define NC 32           // chunks over L
#define CH 32           // chunk size (NC*CH == LL)

typedef unsigned long long ull;
typedef unsigned int u32;

// packed fp32x2 FMA (SASS FFMA2) — PTX-only; IEEE-identical to 2x fmaf
__device__ __forceinline__ ull ffma2(ull a, ull b, ull c) {
    ull d;
    asm("fma.rn.f32x2 %0, %1, %2, %3;" : "=l"(d) : "l"(a), "l"(b), "l"(c));
    return d;
}

// m16n8k16 row.col bf16 MMA, f32 accumulate-in-place
__device__ __forceinline__ void mma16816(float& d0, float& d1, float& d2, float& d3,
                                         uint4 a, uint2 b) {
    asm("mma.sync.aligned.m16n8k16.row.col.f32.bf16.bf16.f32 "
        "{%0,%1,%2,%3}, {%4,%5,%6,%7}, {%8,%9}, {%0,%1,%2,%3};"
        : "+f"(d0), "+f"(d1), "+f"(d2), "+f"(d3)
        : "r"(a.x), "r"(a.y), "r"(a.z), "r"(a.w), "r"(b.x), "r"(b.y));
}

// split a float2 into bf16x2 hi and lo words (x -> low half of word)
__device__ __forceinline__ void split2(float2 p, u32& hi, u32& lo) {
    __nv_bfloat162 hb = __float22bfloat162_rn(p);
    float2 hf = __bfloat1622float2(hb);
    float2 lf = make_float2(p.x - hf.x, p.y - hf.y);
    __nv_bfloat162 lb = __float22bfloat162_rn(lf);
    hi = *(u32*)&hb;
    lo = *(u32*)&lb;
}

// Scratch (device globals: no allocation allowed)
__device__ float g_x[BB * LL * NO];           // 4 MB : x = h @ W1
__device__ int   g_chunk_first[BB * NC * VV];
__device__ int   g_next[BB * NC * VV];
// fragment buffers for tensor-core gemm2
#define NMT 256   // m-tiles (4096/16)
#define NKT 16    // k(col)-tiles of x (256/16)
__device__ uint4 g_xah[NMT * NKT * 32];       // 2 MB  A-frag hi
__device__ uint4 g_xal[NMT * NKT * 32];       // 2 MB  A-frag lo
#define NV8 160   // 1280/8
__device__ uint2 g_wbh[NV8 * 2 * 32];         // 80 KB B-frag hi (kt=2)
__device__ uint2 g_wbl[NV8 * 2 * 32];         // 80 KB B-frag lo

// ---------------------------------------------------------------------------
// GEMM1: x[4096,256] = h[4096,768] @ W1[768,256]  (unchanged FP32/FFMA2)
// ---------------------------------------------------------------------------
__global__ __launch_bounds__(256) void gemm1_kernel(
    const float* __restrict__ h, const float* __restrict__ W1)
{
    __shared__ float As_dup[16][256];
    __shared__ float Bs[16][64];

    const int tid = threadIdx.x;
    const int tx = tid & 15;
    const int ty = tid >> 4;
    const int m0 = blockIdx.y * 128;
    const int n0 = blockIdx.x * 64;

    const int ar = tid >> 1;
    const int ac = (tid & 1) * 8;
    const int br = tid >> 4;
    const int bc = (tid & 15) * 4;

    ull acc[8][2];
#pragma unroll
    for (int i = 0; i < 8; ++i) { acc[i][0] = 0ULL; acc[i][1] = 0ULL; }

    for (int k0 = 0; k0 < NE; k0 += 16) {
#pragma unroll
        for (int half = 0; half < 2; ++half) {
            float4 av = *(const float4*)&h[(m0 + ar) * NE + k0 + ac + half * 4];
            ((float2*)As_dup[ac + half * 4 + 0])[ar] = make_float2(av.x, av.x);
            ((float2*)As_dup[ac + half * 4 + 1])[ar] = make_float2(av.y, av.y);
            ((float2*)As_dup[ac + half * 4 + 2])[ar] = make_float2(av.z, av.z);
            ((float2*)As_dup[ac + half * 4 + 3])[ar] = make_float2(av.w, av.w);
        }
        *(float4*)&Bs[br][bc] = *(const float4*)&W1[(k0 + br) * NO + n0 + bc];
        __syncthreads();

#pragma unroll
        for (int kk = 0; kk < 16; ++kk) {
            const ull* arow = (const ull*)As_dup[kk];
            const ull* brow = (const ull*)Bs[kk];
            ulonglong2 t0 = *(const ulonglong2*)&arow[ty * 8 + 0];
            ulonglong2 t1 = *(const ulonglong2*)&arow[ty * 8 + 2];
            ulonglong2 t2 = *(const ulonglong2*)&arow[ty * 8 + 4];
            ulonglong2 t3 = *(const ulonglong2*)&arow[ty * 8 + 6];
            ulonglong2 u  = *(const ulonglong2*)&brow[tx * 2];
            ull a_[8] = {t0.x, t0.y, t1.x, t1.y, t2.x, t2.y, t3.x, t3.y};
#pragma unroll
            for (int i = 0; i < 8; ++i) {
                acc[i][0] = ffma2(a_[i], u.x, acc[i][0]);
                acc[i][1] = ffma2(a_[i], u.y, acc[i][1]);
            }
        }
        __syncthreads();
    }

#pragma unroll
    for (int i = 0; i < 8; ++i) {
        *(ulonglong2*)&g_x[(m0 + ty * 8 + i) * NO + n0 + tx * 4] =
            make_ulonglong2(acc[i][0], acc[i][1]);
    }
}

// ---------------------------------------------------------------------------
// repack_x: g_x (f32) -> A-fragment hi/lo buffers.
// thread gt = ((mt*NKT + kt)*32 + lane); writes one uint4 per buffer.
// a0:(row g, col t*2) a1:(row g+8) a2:(col +8) a3:(row+8,col+8)
// ---------------------------------------------------------------------------
__global__ __launch_bounds__(256) void repack_x_kernel()
{
    const int gt = blockIdx.x * 256 + threadIdx.x;    // 0..131071
    const int l = gt & 31;
    const int kt = (gt >> 5) & (NKT - 1);
    const int mt = gt >> 9;
    const int g = l >> 2, t = l & 3;

    const int r0 = mt * 16 + g, r1 = r0 + 8;
    const int ca = kt * 16 + t * 2, cb = ca + 8;

    float2 p00 = *(const float2*)&g_x[r0 * NO + ca];
    float2 p10 = *(const float2*)&g_x[r1 * NO + ca];
    float2 p01 = *(const float2*)&g_x[r0 * NO + cb];
    float2 p11 = *(const float2*)&g_x[r1 * NO + cb];

    uint4 hv, lv;
    split2(p00, hv.x, lv.x);
    split2(p10, hv.y, lv.y);
    split2(p01, hv.z, lv.z);
    split2(p11, hv.w, lv.w);
    g_xah[gt] = hv;
    g_xal[gt] = lv;
}

// ---------------------------------------------------------------------------
// repack_w2: W2[32,1280] -> B-fragment hi/lo buffers.
// thread gt = ((v8*2 + kt)*32 + lane); b0:(k t*2, col g) b1:(k t*2+8)
// ---------------------------------------------------------------------------
__global__ __launch_bounds__(256) void repack_w2_kernel(const float* __restrict__ W2)
{
    const int gt = blockIdx.x * 256 + threadIdx.x;    // 0..10239
    const int l = gt & 31;
    const int kt = (gt >> 5) & 1;
    const int v8 = gt >> 6;
    const int g = l >> 2, t = l & 3;

    const int v = v8 * 8 + g;
    const int k0 = kt * 16 + t * 2;

    float2 q0 = make_float2(W2[(k0 + 0) * VV + v], W2[(k0 + 1) * VV + v]);
    float2 q1 = make_float2(W2[(k0 + 8) * VV + v], W2[(k0 + 9) * VV + v]);

    uint2 hv, lv;
    split2(q0, hv.x, lv.x);
    split2(q1, hv.y, lv.y);
    g_wbh[gt] = hv;
    g_wbl[gt] = lv;
}

// ---------------------------------------------------------------------------
// GEMM2 on tensor cores (fallback HMMA): logits[m][n][v] = x[m,n*32:].W2
// Block 128 threads (4 warps) = 128m x 32v, all 8 bins.
// Warp: 2 m-tiles (32m); 4 n8 v-tiles. B frags hoisted across bin loop.
// 2-term bf16 split: D += Ah*Bh + Ah*Bl + Al*Bh  (lo*lo dropped, ~2^-18)
// ---------------------------------------------------------------------------
__global__ __launch_bounds__(128) void gemm2_mma_kernel(float* __restrict__ logits)
{
    const int w = threadIdx.x >> 5;
    const int l = threadIdx.x & 31;
    const int g = l >> 2, t = l & 3;
    const int bx = blockIdx.x;          // 0..39 : v block of 32
    const int by = blockIdx.y;          // 0..31 : m block of 128
    const int mt0 = by * 8 + w * 2;     // warp's first m-tile

    // hoist B fragments (shared by all bins): [v8i][kt], hi and lo
    uint2 Bh[4][2], Bl[4][2];
#pragma unroll
    for (int v8i = 0; v8i < 4; ++v8i)
#pragma unroll
        for (int j = 0; j < 2; ++j) {
            int idx = (((bx * 4 + v8i) * 2 + j) * 32) + l;
            Bh[v8i][j] = g_wbh[idx];
            Bl[v8i][j] = g_wbl[idx];
        }

#pragma unroll 1
    for (int n = 0; n < NB; ++n) {
        uint4 Ah[2][2], Al[2][2];
#pragma unroll
        for (int mi = 0; mi < 2; ++mi)
#pragma unroll
            for (int j = 0; j < 2; ++j) {
                int idx = (((mt0 + mi) * NKT + (2 * n + j)) * 32) + l;
                Ah[mi][j] = g_xah[idx];
                Al[mi][j] = g_xal[idx];
            }

        float acc[2][4][4];
#pragma unroll
        for (int mi = 0; mi < 2; ++mi)
#pragma unroll
            for (int v8i = 0; v8i < 4; ++v8i)
#pragma unroll
                for (int q = 0; q < 4; ++q) acc[mi][v8i][q] = 0.0f;

#pragma unroll
        for (int mi = 0; mi < 2; ++mi)
#pragma unroll
            for (int v8i = 0; v8i < 4; ++v8i)
#pragma unroll
                for (int j = 0; j < 2; ++j) {
                    float* d = acc[mi][v8i];
                    mma16816(d[0], d[1], d[2], d[3], Ah[mi][j], Bh[v8i][j]);
                    mma16816(d[0], d[1], d[2], d[3], Ah[mi][j], Bl[v8i][j]);
                    mma16816(d[0], d[1], d[2], d[3], Al[mi][j], Bh[v8i][j]);
                }

        // store: c0,c1 -> (row g, v t*2..t*2+1); c2,c3 -> (row g+8)
#pragma unroll
        for (int mi = 0; mi < 2; ++mi) {
            const int mlo = (mt0 + mi) * 16 + g;
#pragma unroll
            for (int v8i = 0; v8i < 4; ++v8i) {
                const int v = (bx * 4 + v8i) * 8 + t * 2;
                float* d = acc[mi][v8i];
                *(float2*)&logits[((mlo + 0) * NB + n) * VV + v] = make_float2(d[0], d[1]);
                *(float2*)&logits[((mlo + 8) * NB + n) * VV + v] = make_float2(d[2], d[3]);
            }
        }
    }
}

// ---------------------------------------------------------------------------
// Kernel A: per-chunk first occurrence. Block per (b, c); smem atomicMin.
// ---------------------------------------------------------------------------
__global__ __launch_bounds__(256) void first_occ_kernel(const int* __restrict__ targets)
{
    __shared__ int arr[VV];
    const int b = blockIdx.x >> 5;
    const int c = blockIdx.x & 31;
    const int tid = threadIdx.x;

#pragma unroll
    for (int it = 0; it < 5; ++it) arr[tid + it * 256] = LL;
    __syncthreads();
    if (tid < CH) {
        int j = c * CH + tid;
        atomicMin(&arr[targets[b * LL + j]], j);
    }
    __syncthreads();
#pragma unroll
    for (int it = 0; it < 5; ++it) {
        int idx = tid + it * 256;
        g_chunk_first[(b * NC + c) * VV + idx] = arr[idx];
    }
}

// ---------------------------------------------------------------------------
// Kernel B: exclusive suffix-min over chunks. One thread per (b, v).
// ---------------------------------------------------------------------------
__global__ __launch_bounds__(256) void suffix_kernel()
{
    const int gt = blockIdx.x * 256 + threadIdx.x;   // 0..5119
    const int b = gt / VV;
    const int v = gt - b * VV;

    int cf[NC];
#pragma unroll
    for (int c = 0; c < NC; ++c) cf[c] = g_chunk_first[(b * NC + c) * VV + v];

    int run = LL;
#pragma unroll
    for (int c = NC - 1; c >= 0; --c) {
        g_next[(b * NC + c) * VV + v] = run;
        run = min(run, cf[c]);
    }
}

// ---------------------------------------------------------------------------
// Kernel C: tte + censor mask. Block per (b, c, vhalf), 160 threads, 4 v each.
// ---------------------------------------------------------------------------
__global__ __launch_bounds__(160) void tte_mask_kernel(
    const int* __restrict__ targets,
    const float* __restrict__ age,
    const float* __restrict__ targets_age,
    float* __restrict__ out_tte,
    float* __restrict__ out_mask)
{
    __shared__ float ta_s[LL];
    __shared__ int ts[CH];
    __shared__ float ag[CH];

    const int b = blockIdx.x >> 6;
    const int rem = blockIdx.x & 63;
    const int c = rem >> 1;
    const int half = rem & 1;
    const int tid = threadIdx.x;        // 0..159

    for (int idx = tid; idx < LL; idx += 160)
        ta_s[idx] = targets_age[b * LL + idx];
    if (tid < CH) {
        int i = c * CH + tid;
        ts[tid] = targets[b * LL + i];
        ag[tid] = age[b * LL + i];
    }
    __syncthreads();

    const int vb = half * 640 + tid * 4;
    int4 c4 = *(const int4*)&g_next[(b * NC + c) * VV + vb];
    int cur0 = c4.x, cur1 = c4.y, cur2 = c4.z, cur3 = c4.w;

    for (int jj = CH - 1; jj >= 0; --jj) {
        const int i = c * CH + jj;
        const int t = ts[jj];
        const float ai = ag[jj];

        if (t == vb + 0) cur0 = i;
        if (t == vb + 1) cur1 = i;
        if (t == vb + 2) cur2 = i;
        if (t == vb + 3) cur3 = i;

        float tte[4];
        bool nev[4];
        int curs[4] = {cur0, cur1, cur2, cur3};
#pragma unroll
        for (int q = 0; q < 4; ++q) {
            int vv = vb + q;
            int idxr = curs[q];
            if (vv == 0 && i > 0) idxr = 0;  // reference's where(upper, targets, 0) quirk
            bool ne = (idxr == LL);
            int idx = ne ? (LL - 1) : idxr;
            tte[q] = ta_s[idx] - ai;
            nev[q] = ne;
        }

        const int row = b * LL + i;
        *(float4*)&out_tte[row * VV + vb] = make_float4(tte[0], tte[1], tte[2], tte[3]);

        int bin[4];
        bool valid[4];
#pragma unroll
        for (int q = 0; q < 4; ++q) {
            float tq = tte[q];
            valid[q] = (tq >= 0.0f) && (tq < 10.0f);
            bin[q] = (tq >= 1.25f) + (tq >= 2.5f) + (tq >= 3.75f) + (tq >= 5.0f)
                   + (tq >= 6.25f) + (tq >= 7.5f) + (tq >= 8.75f);
        }

        const int mbase = row * NB * VV + vb;
#pragma unroll
        for (int n = 0; n < 8; ++n) {
            float4 mv;
            mv.x = (nev[0] || (valid[0] && bin[0] == n)) ? 1.0f : 0.0f;
            mv.y = (nev[1] || (valid[1] && bin[1] == n)) ? 1.0f : 0.0f;
            mv.z = (nev[2] || (valid[2] && bin[2] == n)) ? 1.0f : 0.0f;
            mv.w = (nev[3] || (valid[3] && bin[3] == n)) ? 1.0f : 0.0f;
            *(float4*)&out_mask[mbase + n * VV] = mv;
        }
    }
}

// ---------------------------------------------------------------------------
extern "C" void kernel_launch(void* const* d_in, const int* in_sizes, int n_in,
                              void* d_out, int out_size)
{
    const float* h   = (const float*)d_in[0];  // (B,L,768) f32
    const float* age = (const float*)d_in[1];  // (B,L) f32
    const float* ta  = (const float*)d_in[2];  // (B,L) f32 targets_age
    // d_in[3] = delta_t (unused by outputs)
    const int*   tg  = (const int*)d_in[4];    // (B,L) i32 targets
    const float* W1  = (const float*)d_in[5];  // (768,256) f32
    const float* W2  = (const float*)d_in[6];  // (32,1280) f32

    float* out = (float*)d_out;
    float* out_logits = out;                                  // B*L*8*V
    float* out_tte    = out + (size_t)BB * LL * NB * VV;      // B*L*V
    float* out_mask   = out_tte + (size_t)BB * LL * VV;       // B*L*8*V

    // order: slot 4 (ncu capture) = gemm2_mma
    repack_w2_kernel<<<40, 256>>>(W2);
    gemm1_kernel<<<dim3(NO / 64, (BB * LL) / 128), 256>>>(h, W1);
    repack_x_kernel<<<512, 256>>>();
    gemm2_mma_kernel<<<dim3(VV / 32, (BB * LL) / 128), 128>>>(out_logits);
    first_occ_kernel<<<BB * NC, 256>>>(tg);
    suffix_kernel<<<(BB * VV) / 256, 256>>>();
    tte_mask_kernel<<<BB * NC * 2, 160>>>(tg, age, ta, out_tte, out_mask);
}

// round 10
// speedup vs baseline: 1.6602x; 1.4503x over previous
#include <cuda_runtime.h>
#include <cuda_bf16.h>

#define BB 4
#define LL 1024
#define VV 1280
#define NE 768
#define NB 8
#define NH 32
#define NO 256          // NB*NH
#define NC 32           // chunks over L
#define CH 32           // chunk size (NC*CH == LL)

typedef unsigned long long ull;
typedef unsigned int u32;

// m16n8k16 row.col bf16 MMA, f32 accumulate-in-place
__device__ __forceinline__ void mma16816(float& d0, float& d1, float& d2, float& d3,
                                         uint4 a, uint2 b) {
    asm("mma.sync.aligned.m16n8k16.row.col.f32.bf16.bf16.f32 "
        "{%0,%1,%2,%3}, {%4,%5,%6,%7}, {%8,%9}, {%0,%1,%2,%3};"
        : "+f"(d0), "+f"(d1), "+f"(d2), "+f"(d3)
        : "r"(a.x), "r"(a.y), "r"(a.z), "r"(a.w), "r"(b.x), "r"(b.y));
}

// split a float2 into bf16x2 hi and lo words (x -> low half of word)
__device__ __forceinline__ void split2(float2 p, u32& hi, u32& lo) {
    __nv_bfloat162 hb = __float22bfloat162_rn(p);
    float2 hf = __bfloat1622float2(hb);
    float2 lf = make_float2(p.x - hf.x, p.y - hf.y);
    __nv_bfloat162 lb = __float22bfloat162_rn(lf);
    hi = *(u32*)&hb;
    lo = *(u32*)&lb;
}

// Scratch (device globals: no allocation allowed)
__device__ int   g_chunk_first[BB * NC * VV];
__device__ int   g_next[BB * NC * VV];
// fragment buffers
#define NMT 256   // m-tiles (4096/16)
#define NKT 16    // k(col)-tiles of x (256/16)
#define NKT1 48   // k-tiles over NE (768/16)
__device__ uint4 g_xah[NMT * NKT * 32];        // 2 MB  x A-frag hi
__device__ uint4 g_xal[NMT * NKT * 32];        // 2 MB  x A-frag lo
__device__ uint4 g_hah[NMT * NKT1 * 32];       // 6.3 MB h A-frag hi
__device__ uint4 g_hal[NMT * NKT1 * 32];       // 6.3 MB h A-frag lo
#define NV8 160   // 1280/8
__device__ uint2 g_wbh[NV8 * 2 * 32];          // W2 B-frag hi
__device__ uint2 g_wbl[NV8 * 2 * 32];          // W2 B-frag lo
#define N81 32    // 256/8
__device__ uint2 g_w1bh[N81 * NKT1 * 32];      // W1 B-frag hi
__device__ uint2 g_w1bl[N81 * NKT1 * 32];      // W1 B-frag lo

// ---------------------------------------------------------------------------
// repack_h: h (f32, 4096x768) -> A-fragment hi/lo buffers (NKT1=48).
// ---------------------------------------------------------------------------
__global__ __launch_bounds__(256) void repack_h_kernel(const float* __restrict__ h)
{
    const int gt = blockIdx.x * 256 + threadIdx.x;    // 0..393215
    const int l = gt & 31;
    const int kt = (gt >> 5) % NKT1;
    const int mt = gt / (NKT1 * 32);
    const int g = l >> 2, t = l & 3;

    const int r0 = mt * 16 + g, r1 = r0 + 8;
    const int ca = kt * 16 + t * 2, cb = ca + 8;

    float2 p00 = *(const float2*)&h[r0 * NE + ca];
    float2 p10 = *(const float2*)&h[r1 * NE + ca];
    float2 p01 = *(const float2*)&h[r0 * NE + cb];
    float2 p11 = *(const float2*)&h[r1 * NE + cb];

    uint4 hv, lv;
    split2(p00, hv.x, lv.x);
    split2(p10, hv.y, lv.y);
    split2(p01, hv.z, lv.z);
    split2(p11, hv.w, lv.w);
    g_hah[gt] = hv;
    g_hal[gt] = lv;
}

// ---------------------------------------------------------------------------
// repack_w1: W1[768,256] -> B-fragment hi/lo buffers (col = output o).
// ---------------------------------------------------------------------------
__global__ __launch_bounds__(256) void repack_w1_kernel(const float* __restrict__ W1)
{
    const int gt = blockIdx.x * 256 + threadIdx.x;    // 0..49151
    const int l = gt & 31;
    const int kt = (gt >> 5) % NKT1;
    const int n8 = gt / (NKT1 * 32);
    const int g = l >> 2, t = l & 3;

    const int o = n8 * 8 + g;
    const int k0 = kt * 16 + t * 2;

    float2 q0 = make_float2(W1[(k0 + 0) * NO + o], W1[(k0 + 1) * NO + o]);
    float2 q1 = make_float2(W1[(k0 + 8) * NO + o], W1[(k0 + 9) * NO + o]);

    uint2 hv, lv;
    split2(q0, hv.x, lv.x);
    split2(q1, hv.y, lv.y);
    g_w1bh[gt] = hv;
    g_w1bl[gt] = lv;
}

// ---------------------------------------------------------------------------
// repack_w2: W2[32,1280] -> B-fragment hi/lo buffers. (verified R9)
// ---------------------------------------------------------------------------
__global__ __launch_bounds__(256) void repack_w2_kernel(const float* __restrict__ W2)
{
    const int gt = blockIdx.x * 256 + threadIdx.x;    // 0..10239
    const int l = gt & 31;
    const int kt = (gt >> 5) & 1;
    const int v8 = gt >> 6;
    const int g = l >> 2, t = l & 3;

    const int v = v8 * 8 + g;
    const int k0 = kt * 16 + t * 2;

    float2 q0 = make_float2(W2[(k0 + 0) * VV + v], W2[(k0 + 1) * VV + v]);
    float2 q1 = make_float2(W2[(k0 + 8) * VV + v], W2[(k0 + 9) * VV + v]);

    uint2 hv, lv;
    split2(q0, hv.x, lv.x);
    split2(q1, hv.y, lv.y);
    g_wbh[gt] = hv;
    g_wbl[gt] = lv;
}

// ---------------------------------------------------------------------------
// GEMM1 on tensor cores: x = h @ W1, writing gemm2's A-fragments DIRECTLY
// (C-frag layout == bf16x2 A-frag packing; g_x / repack_x eliminated).
// Block 256 thr (8 warps) = 128m x 64n. Warp = 2 m-tiles x 2 out-ktiles
// (4 n8-tiles). K-loop 48 iters, register double-buffer prefetch.
// 3-term split: D += Ah*Bh + Ah*Bl + Al*Bh.
// ---------------------------------------------------------------------------
__global__ __launch_bounds__(256) void gemm1_mma_kernel()
{
    const int w = threadIdx.x >> 5;
    const int l = threadIdx.x & 31;
    const int mw = w & 3;
    const int nw = w >> 2;
    const int mt0 = blockIdx.y * 8 + mw * 2;
    const int kto0 = blockIdx.x * 4 + nw * 2;
    const int n80 = kto0 * 2;

    float acc[2][4][4];
#pragma unroll
    for (int mi = 0; mi < 2; ++mi)
#pragma unroll
        for (int i = 0; i < 4; ++i)
#pragma unroll
            for (int q = 0; q < 4; ++q) acc[mi][i][q] = 0.0f;

    uint4 Ah[2][2], Al[2][2];   // [buf][mi]
    uint2 Bh[2][4], Bl[2][4];   // [buf][n8i]

#define LOAD_A(kt, buf) do { \
    _Pragma("unroll") \
    for (int mi = 0; mi < 2; ++mi) { \
        int idx = ((mt0 + mi) * NKT1 + (kt)) * 32 + l; \
        Ah[buf][mi] = g_hah[idx]; Al[buf][mi] = g_hal[idx]; \
    } } while (0)
#define LOAD_B(kt, buf) do { \
    _Pragma("unroll") \
    for (int i = 0; i < 4; ++i) { \
        int idx = ((n80 + i) * NKT1 + (kt)) * 32 + l; \
        Bh[buf][i] = g_w1bh[idx]; Bl[buf][i] = g_w1bl[idx]; \
    } } while (0)
#define DO_MMA(buf) do { \
    _Pragma("unroll") \
    for (int mi = 0; mi < 2; ++mi) \
    _Pragma("unroll") \
    for (int i = 0; i < 4; ++i) { \
        float* d = acc[mi][i]; \
        mma16816(d[0], d[1], d[2], d[3], Ah[buf][mi], Bh[buf][i]); \
        mma16816(d[0], d[1], d[2], d[3], Ah[buf][mi], Bl[buf][i]); \
        mma16816(d[0], d[1], d[2], d[3], Al[buf][mi], Bh[buf][i]); \
    } } while (0)

    LOAD_A(0, 0); LOAD_B(0, 0);
#pragma unroll 1
    for (int kt = 0; kt < NKT1; kt += 2) {
        LOAD_A(kt + 1, 1); LOAD_B(kt + 1, 1);
        DO_MMA(0);
        if (kt + 2 < NKT1) { LOAD_A(kt + 2, 0); LOAD_B(kt + 2, 0); }
        DO_MMA(1);
    }
#undef LOAD_A
#undef LOAD_B
#undef DO_MMA

    // epilogue: C-frags -> x A-frags (hi/lo), same layout repack_x produced
#pragma unroll
    for (int mi = 0; mi < 2; ++mi)
#pragma unroll
        for (int kto = 0; kto < 2; ++kto) {
            const float* da = acc[mi][kto * 2 + 0];
            const float* db = acc[mi][kto * 2 + 1];
            uint4 hv, lv;
            split2(make_float2(da[0], da[1]), hv.x, lv.x);
            split2(make_float2(da[2], da[3]), hv.y, lv.y);
            split2(make_float2(db[0], db[1]), hv.z, lv.z);
            split2(make_float2(db[2], db[3]), hv.w, lv.w);
            int idx = ((mt0 + mi) * NKT + (kto0 + kto)) * 32 + l;
            g_xah[idx] = hv;
            g_xal[idx] = lv;
        }
}

// ---------------------------------------------------------------------------
// GEMM2 on tensor cores (verified R9, unchanged): logits from x-frags.
// ---------------------------------------------------------------------------
__global__ __launch_bounds__(128) void gemm2_mma_kernel(float* __restrict__ logits)
{
    const int w = threadIdx.x >> 5;
    const int l = threadIdx.x & 31;
    const int g = l >> 2, t = l & 3;
    const int bx = blockIdx.x;          // 0..39 : v block of 32
    const int by = blockIdx.y;          // 0..31 : m block of 128
    const int mt0 = by * 8 + w * 2;

    uint2 Bh[4][2], Bl[4][2];
#pragma unroll
    for (int v8i = 0; v8i < 4; ++v8i)
#pragma unroll
        for (int j = 0; j < 2; ++j) {
            int idx = (((bx * 4 + v8i) * 2 + j) * 32) + l;
            Bh[v8i][j] = g_wbh[idx];
            Bl[v8i][j] = g_wbl[idx];
        }

#pragma unroll 1
    for (int n = 0; n < NB; ++n) {
        uint4 Ah[2][2], Al[2][2];
#pragma unroll
        for (int mi = 0; mi < 2; ++mi)
#pragma unroll
            for (int j = 0; j < 2; ++j) {
                int idx = (((mt0 + mi) * NKT + (2 * n + j)) * 32) + l;
                Ah[mi][j] = g_xah[idx];
                Al[mi][j] = g_xal[idx];
            }

        float acc[2][4][4];
#pragma unroll
        for (int mi = 0; mi < 2; ++mi)
#pragma unroll
            for (int v8i = 0; v8i < 4; ++v8i)
#pragma unroll
                for (int q = 0; q < 4; ++q) acc[mi][v8i][q] = 0.0f;

#pragma unroll
        for (int mi = 0; mi < 2; ++mi)
#pragma unroll
            for (int v8i = 0; v8i < 4; ++v8i)
#pragma unroll
                for (int j = 0; j < 2; ++j) {
                    float* d = acc[mi][v8i];
                    mma16816(d[0], d[1], d[2], d[3], Ah[mi][j], Bh[v8i][j]);
                    mma16816(d[0], d[1], d[2], d[3], Ah[mi][j], Bl[v8i][j]);
                    mma16816(d[0], d[1], d[2], d[3], Al[mi][j], Bh[v8i][j]);
                }

#pragma unroll
        for (int mi = 0; mi < 2; ++mi) {
            const int mlo = (mt0 + mi) * 16 + g;
#pragma unroll
            for (int v8i = 0; v8i < 4; ++v8i) {
                const int v = (bx * 4 + v8i) * 8 + t * 2;
                float* d = acc[mi][v8i];
                *(float2*)&logits[((mlo + 0) * NB + n) * VV + v] = make_float2(d[0], d[1]);
                *(float2*)&logits[((mlo + 8) * NB + n) * VV + v] = make_float2(d[2], d[3]);
            }
        }
    }
}

// ---------------------------------------------------------------------------
// Kernel A: per-chunk first occurrence. Block per (b, c); smem atomicMin.
// ---------------------------------------------------------------------------
__global__ __launch_bounds__(256) void first_occ_kernel(const int* __restrict__ targets)
{
    __shared__ int arr[VV];
    const int b = blockIdx.x >> 5;
    const int c = blockIdx.x & 31;
    const int tid = threadIdx.x;

#pragma unroll
    for (int it = 0; it < 5; ++it) arr[tid + it * 256] = LL;
    __syncthreads();
    if (tid < CH) {
        int j = c * CH + tid;
        atomicMin(&arr[targets[b * LL + j]], j);
    }
    __syncthreads();
#pragma unroll
    for (int it = 0; it < 5; ++it) {
        int idx = tid + it * 256;
        g_chunk_first[(b * NC + c) * VV + idx] = arr[idx];
    }
}

// ---------------------------------------------------------------------------
// Kernel B: exclusive suffix-min over chunks. One thread per (b, v).
// ---------------------------------------------------------------------------
__global__ __launch_bounds__(256) void suffix_kernel()
{
    const int gt = blockIdx.x * 256 + threadIdx.x;   // 0..5119
    const int b = gt / VV;
    const int v = gt - b * VV;

    int cf[NC];
#pragma unroll
    for (int c = 0; c < NC; ++c) cf[c] = g_chunk_first[(b * NC + c) * VV + v];

    int run = LL;
#pragma unroll
    for (int c = NC - 1; c >= 0; --c) {
        g_next[(b * NC + c) * VV + v] = run;
        run = min(run, cf[c]);
    }
}

// ---------------------------------------------------------------------------
// Kernel C: tte + censor mask. Block per (b, c, vhalf), 160 threads, 4 v each.
// ---------------------------------------------------------------------------
__global__ __launch_bounds__(160) void tte_mask_kernel(
    const int* __restrict__ targets,
    const float* __restrict__ age,
    const float* __restrict__ targets_age,
    float* __restrict__ out_tte,
    float* __restrict__ out_mask)
{
    __shared__ float ta_s[LL];
    __shared__ int ts[CH];
    __shared__ float ag[CH];

    const int b = blockIdx.x >> 6;
    const int rem = blockIdx.x & 63;
    const int c = rem >> 1;
    const int half = rem & 1;
    const int tid = threadIdx.x;        // 0..159

    for (int idx = tid; idx < LL; idx += 160)
        ta_s[idx] = targets_age[b * LL + idx];
    if (tid < CH) {
        int i = c * CH + tid;
        ts[tid] = targets[b * LL + i];
        ag[tid] = age[b * LL + i];
    }
    __syncthreads();

    const int vb = half * 640 + tid * 4;
    int4 c4 = *(const int4*)&g_next[(b * NC + c) * VV + vb];
    int cur0 = c4.x, cur1 = c4.y, cur2 = c4.z, cur3 = c4.w;

    for (int jj = CH - 1; jj >= 0; --jj) {
        const int i = c * CH + jj;
        const int t = ts[jj];
        const float ai = ag[jj];

        if (t == vb + 0) cur0 = i;
        if (t == vb + 1) cur1 = i;
        if (t == vb + 2) cur2 = i;
        if (t == vb + 3) cur3 = i;

        float tte[4];
        bool nev[4];
        int curs[4] = {cur0, cur1, cur2, cur3};
#pragma unroll
        for (int q = 0; q < 4; ++q) {
            int vv = vb + q;
            int idxr = curs[q];
            if (vv == 0 && i > 0) idxr = 0;  // reference's where(upper, targets, 0) quirk
            bool ne = (idxr == LL);
            int idx = ne ? (LL - 1) : idxr;
            tte[q] = ta_s[idx] - ai;
            nev[q] = ne;
        }

        const int row = b * LL + i;
        *(float4*)&out_tte[row * VV + vb] = make_float4(tte[0], tte[1], tte[2], tte[3]);

        int bin[4];
        bool valid[4];
#pragma unroll
        for (int q = 0; q < 4; ++q) {
            float tq = tte[q];
            valid[q] = (tq >= 0.0f) && (tq < 10.0f);
            bin[q] = (tq >= 1.25f) + (tq >= 2.5f) + (tq >= 3.75f) + (tq >= 5.0f)
                   + (tq >= 6.25f) + (tq >= 7.5f) + (tq >= 8.75f);
        }

        const int mbase = row * NB * VV + vb;
#pragma unroll
        for (int n = 0; n < 8; ++n) {
            float4 mv;
            mv.x = (nev[0] || (valid[0] && bin[0] == n)) ? 1.0f : 0.0f;
            mv.y = (nev[1] || (valid[1] && bin[1] == n)) ? 1.0f : 0.0f;
            mv.z = (nev[2] || (valid[2] && bin[2] == n)) ? 1.0f : 0.0f;
            mv.w = (nev[3] || (valid[3] && bin[3] == n)) ? 1.0f : 0.0f;
            *(float4*)&out_mask[mbase + n * VV] = mv;
        }
    }
}

// ---------------------------------------------------------------------------
extern "C" void kernel_launch(void* const* d_in, const int* in_sizes, int n_in,
                              void* d_out, int out_size)
{
    const float* h   = (const float*)d_in[0];  // (B,L,768) f32
    const float* age = (const float*)d_in[1];  // (B,L) f32
    const float* ta  = (const float*)d_in[2];  // (B,L) f32 targets_age
    // d_in[3] = delta_t (unused by outputs)
    const int*   tg  = (const int*)d_in[4];    // (B,L) i32 targets
    const float* W1  = (const float*)d_in[5];  // (768,256) f32
    const float* W2  = (const float*)d_in[6];  // (32,1280) f32

    float* out = (float*)d_out;
    float* out_logits = out;                                  // B*L*8*V
    float* out_tte    = out + (size_t)BB * LL * NB * VV;      // B*L*V
    float* out_mask   = out_tte + (size_t)BB * LL * VV;       // B*L*8*V

    // slot 4 (ncu capture) = gemm1_mma
    repack_w2_kernel<<<40, 256>>>(W2);
    repack_h_kernel<<<(NMT * NKT1 * 32) / 256, 256>>>(h);
    repack_w1_kernel<<<(N81 * NKT1 * 32) / 256, 256>>>(W1);
    gemm1_mma_kernel<<<dim3(NKT / 4, NMT / 8), 256>>>();
    gemm2_mma_kernel<<<dim3(VV / 32, (BB * LL) / 128), 128>>>(out_logits);
    first_occ_kernel<<<BB * NC, 256>>>(tg);
    suffix_kernel<<<(BB * VV) / 256, 256>>>();
    tte_mask_kernel<<<BB * NC * 2, 160>>>(tg, age, ta, out_tte, out_mask);
}